// round 1
// baseline (speedup 1.0000x reference)
#include <cuda_runtime.h>
#include <cuda_bf16.h>
#include <math.h>
#include <math_constants.h>

// Problem constants
#define BATCH 2
#define SEQ   2048
#define DMODEL 2048
#define NHEAD 16
#define HDIM  128
#define ROWS  (BATCH * SEQ)          // 4096
#define QKV_N (3 * DMODEL)           // 6144

// Scratch (allocation-free rule: __device__ globals)
__device__ float g_qkv[(size_t)ROWS * QKV_N];   // [4096, 6144]
__device__ float g_att[(size_t)ROWS * DMODEL];  // [4096, 2048]

// ---------------------------------------------------------------------------
// SGEMM: C[M,N] = A[M,K] @ B[K,N] + bias[N]   (all row-major, fp32)
// 128x128 block tile, BK=16, 8x8 per-thread microtile, 256 threads.
// ---------------------------------------------------------------------------
#define BM 128
#define BN 128
#define BK 16
#define TM 8
#define TN 8

__global__ __launch_bounds__(256, 2)
void sgemm_bias(const float* __restrict__ A, const float* __restrict__ B,
                const float* __restrict__ bias, float* __restrict__ C,
                int M, int N, int K) {
    __shared__ float As[BK][BM];   // transposed A tile
    __shared__ float Bs[BK][BN];

    const int tid = threadIdx.x;
    const int tr = tid / 16;       // 0..15
    const int tc = tid % 16;       // 0..15
    const int rowBase = blockIdx.y * BM;
    const int colBase = blockIdx.x * BN;

    // A tile loader mapping: 128 rows x 16 cols, float4 along K
    const int arow = tid / 4;            // 0..63  (x2 iters -> 128 rows)
    const int acol = (tid % 4) * 4;      // 0,4,8,12
    // B tile loader mapping: 16 rows x 128 cols, float4 along N
    const int brow = tid / 32;           // 0..7   (x2 iters -> 16 rows)
    const int bcol = (tid % 32) * 4;     // 0..124

    float acc[TM][TN];
    #pragma unroll
    for (int i = 0; i < TM; i++)
        #pragma unroll
        for (int j = 0; j < TN; j++) acc[i][j] = 0.0f;

    for (int k0 = 0; k0 < K; k0 += BK) {
        #pragma unroll
        for (int it = 0; it < 2; it++) {
            int r = arow + it * 64;
            float4 v = *(const float4*)&A[(size_t)(rowBase + r) * K + (k0 + acol)];
            As[acol + 0][r] = v.x;
            As[acol + 1][r] = v.y;
            As[acol + 2][r] = v.z;
            As[acol + 3][r] = v.w;
        }
        #pragma unroll
        for (int it = 0; it < 2; it++) {
            int r = brow + it * 8;
            float4 v = *(const float4*)&B[(size_t)(k0 + r) * N + (colBase + bcol)];
            *(float4*)&Bs[r][bcol] = v;
        }
        __syncthreads();

        #pragma unroll
        for (int k = 0; k < BK; k++) {
            float rm[TM], rn[TN];
            #pragma unroll
            for (int i = 0; i < TM; i++) rm[i] = As[k][tr * TM + i];
            #pragma unroll
            for (int j = 0; j < TN; j++) rn[j] = Bs[k][tc * TN + j];
            #pragma unroll
            for (int i = 0; i < TM; i++)
                #pragma unroll
                for (int j = 0; j < TN; j++)
                    acc[i][j] = fmaf(rm[i], rn[j], acc[i][j]);
        }
        __syncthreads();
    }

    #pragma unroll
    for (int i = 0; i < TM; i++) {
        int r = rowBase + tr * TM + i;
        #pragma unroll
        for (int j = 0; j < TN; j += 4) {
            int c = colBase + tc * TN + j;
            float4 v;
            v.x = acc[i][j + 0] + bias[c + 0];
            v.y = acc[i][j + 1] + bias[c + 1];
            v.z = acc[i][j + 2] + bias[c + 2];
            v.w = acc[i][j + 3] + bias[c + 3];
            *(float4*)&C[(size_t)r * N + c] = v;
        }
    }
}

// ---------------------------------------------------------------------------
// Flash-attention style causal attention, fp32.
// Grid: (S/64 q-tiles, H, B). Block: 256 threads.
// Q tile 64x128, loop over K/V tiles of 64 rows (kt <= qt).
// Per-thread O accumulator: 4 rows x 8 cols (32 regs).
// Dynamic smem: Qs/Ks/Vs 64x132 each, Ss 64x68, stats 3x64.
// ---------------------------------------------------------------------------
#define QT 64
#define QPAD 132
#define SPAD 68
#define ATTN_SMEM_FLOATS (3 * QT * QPAD + QT * SPAD + 3 * QT)
#define ATTN_SMEM_BYTES  (ATTN_SMEM_FLOATS * 4)

__global__ __launch_bounds__(256, 1)
void attn_kernel(const float* __restrict__ qkv, float* __restrict__ out) {
    extern __shared__ float sm[];
    float* Qs = sm;                         // 64*132
    float* Ks = Qs + QT * QPAD;             // 64*132
    float* Vs = Ks + QT * QPAD;             // 64*132
    float* Ss = Vs + QT * QPAD;             // 64*68
    float* ms = Ss + QT * SPAD;             // 64
    float* ls = ms + QT;                    // 64
    float* fs = ls + QT;                    // 64

    const int qt  = blockIdx.x;             // 0..31
    const int h   = blockIdx.y;             // 0..15
    const int b   = blockIdx.z;             // 0..1
    const int tid = threadIdx.x;
    const int ty  = tid / 16;               // 0..15
    const int tx  = tid % 16;               // 0..15
    const int r0  = ty * 4;                 // S-rows / O-rows owned
    const int c0  = tx * 4;                 // S-cols owned
    const int oc0 = tx * 8;                 // O-cols owned

    const float scale = 0.08838834764831845f;   // 1/sqrt(128)
    const size_t base = (size_t)b * SEQ * QKV_N;
    const int hoff = h * HDIM;

    // Load Q tile (coalesced float4)
    for (int idx = tid; idx < QT * 32; idx += 256) {
        int r  = idx / 32;
        int d4 = (idx % 32) * 4;
        float4 v = *(const float4*)&qkv[base + (size_t)(qt * QT + r) * QKV_N + hoff + d4];
        *(float4*)&Qs[r * QPAD + d4] = v;
    }
    if (tid < QT) { ms[tid] = -CUDART_INF_F; ls[tid] = 0.0f; }

    float O[4][8];
    #pragma unroll
    for (int i = 0; i < 4; i++)
        #pragma unroll
        for (int j = 0; j < 8; j++) O[i][j] = 0.0f;

    for (int kt = 0; kt <= qt; kt++) {
        __syncthreads();   // prev iter done with Ks/Vs/Ss; Q/stats visible on iter 0
        for (int idx = tid; idx < QT * 32; idx += 256) {
            int r  = idx / 32;
            int d4 = (idx % 32) * 4;
            size_t rowoff = base + (size_t)(kt * QT + r) * QKV_N + hoff;
            *(float4*)&Ks[r * QPAD + d4] = *(const float4*)&qkv[rowoff + DMODEL + d4];
            *(float4*)&Vs[r * QPAD + d4] = *(const float4*)&qkv[rowoff + 2 * DMODEL + d4];
        }
        __syncthreads();

        // S = scale * Q K^T  (4x4 per thread)
        float acc[4][4];
        #pragma unroll
        for (int i = 0; i < 4; i++)
            #pragma unroll
            for (int j = 0; j < 4; j++) acc[i][j] = 0.0f;

        for (int d = 0; d < HDIM; d += 4) {
            float4 qv[4], kv[4];
            #pragma unroll
            for (int i = 0; i < 4; i++) qv[i] = *(float4*)&Qs[(r0 + i) * QPAD + d];
            #pragma unroll
            for (int j = 0; j < 4; j++) kv[j] = *(float4*)&Ks[(c0 + j) * QPAD + d];
            #pragma unroll
            for (int i = 0; i < 4; i++)
                #pragma unroll
                for (int j = 0; j < 4; j++) {
                    acc[i][j] = fmaf(qv[i].x, kv[j].x, acc[i][j]);
                    acc[i][j] = fmaf(qv[i].y, kv[j].y, acc[i][j]);
                    acc[i][j] = fmaf(qv[i].z, kv[j].z, acc[i][j]);
                    acc[i][j] = fmaf(qv[i].w, kv[j].w, acc[i][j]);
                }
        }

        const bool diag = (kt == qt);
        #pragma unroll
        for (int i = 0; i < 4; i++)
            #pragma unroll
            for (int j = 0; j < 4; j++) {
                float s = acc[i][j] * scale;
                if (diag && (c0 + j) > (r0 + i)) s = -CUDART_INF_F;
                Ss[(r0 + i) * SPAD + (c0 + j)] = s;
            }
        __syncthreads();

        // Row-wise online softmax stats (one thread per row)
        if (tid < QT) {
            float m_old = ms[tid];
            float m = m_old;
            for (int c = 0; c < QT; c++) m = fmaxf(m, Ss[tid * SPAD + c]);
            float f = expf(m_old - m);
            float l = ls[tid] * f;
            for (int c = 0; c < QT; c++) {
                float p = expf(Ss[tid * SPAD + c] - m);
                Ss[tid * SPAD + c] = p;
                l += p;
            }
            ms[tid] = m; ls[tid] = l; fs[tid] = f;
        }
        __syncthreads();

        // Rescale O, then O += P @ V
        float f[4];
        #pragma unroll
        for (int i = 0; i < 4; i++) f[i] = fs[r0 + i];
        #pragma unroll
        for (int i = 0; i < 4; i++)
            #pragma unroll
            for (int j = 0; j < 8; j++) O[i][j] *= f[i];

        for (int k = 0; k < QT; k++) {
            float p[4];
            #pragma unroll
            for (int i = 0; i < 4; i++) p[i] = Ss[(r0 + i) * SPAD + k];
            float4 v0 = *(float4*)&Vs[k * QPAD + oc0];
            float4 v1 = *(float4*)&Vs[k * QPAD + oc0 + 4];
            #pragma unroll
            for (int i = 0; i < 4; i++) {
                O[i][0] = fmaf(p[i], v0.x, O[i][0]);
                O[i][1] = fmaf(p[i], v0.y, O[i][1]);
                O[i][2] = fmaf(p[i], v0.z, O[i][2]);
                O[i][3] = fmaf(p[i], v0.w, O[i][3]);
                O[i][4] = fmaf(p[i], v1.x, O[i][4]);
                O[i][5] = fmaf(p[i], v1.y, O[i][5]);
                O[i][6] = fmaf(p[i], v1.z, O[i][6]);
                O[i][7] = fmaf(p[i], v1.w, O[i][7]);
            }
        }
    }

    // Epilogue: O /= l, write [b, q, h*128 + d]
    float inv[4];
    #pragma unroll
    for (int i = 0; i < 4; i++) inv[i] = 1.0f / ls[r0 + i];
    size_t obase = ((size_t)b * SEQ + (size_t)qt * QT) * DMODEL + hoff;
    #pragma unroll
    for (int i = 0; i < 4; i++) {
        #pragma unroll
        for (int j = 0; j < 8; j += 4) {
            float4 v;
            v.x = O[i][j + 0] * inv[i];
            v.y = O[i][j + 1] * inv[i];
            v.z = O[i][j + 2] * inv[i];
            v.w = O[i][j + 3] * inv[i];
            *(float4*)&out[obase + (size_t)(r0 + i) * DMODEL + oc0 + j] = v;
        }
    }
}

// ---------------------------------------------------------------------------
// Launch
// ---------------------------------------------------------------------------
extern "C" void kernel_launch(void* const* d_in, const int* in_sizes, int n_in,
                              void* d_out, int out_size) {
    const float* x     = (const float*)d_in[0];
    const float* Wqkv  = (const float*)d_in[1];
    const float* bqkv  = (const float*)d_in[2];
    const float* Wproj = (const float*)d_in[3];
    const float* bproj = (const float*)d_in[4];
    float* out = (float*)d_out;

    float* qkv;
    float* att;
    cudaGetSymbolAddress((void**)&qkv, g_qkv);
    cudaGetSymbolAddress((void**)&att, g_att);

    cudaFuncSetAttribute(attn_kernel, cudaFuncAttributeMaxDynamicSharedMemorySize,
                         ATTN_SMEM_BYTES);

    // 1) QKV GEMM: [4096,2048] @ [2048,6144] + bqkv
    {
        dim3 grid(QKV_N / BN, ROWS / BM);
        sgemm_bias<<<grid, 256>>>(x, Wqkv, bqkv, qkv, ROWS, QKV_N, DMODEL);
    }
    // 2) Causal attention
    {
        dim3 grid(SEQ / QT, NHEAD, BATCH);
        attn_kernel<<<grid, 256, ATTN_SMEM_BYTES>>>(qkv, att);
    }
    // 3) Proj GEMM: [4096,2048] @ [2048,2048] + bproj
    {
        dim3 grid(DMODEL / BN, ROWS / BM);
        sgemm_bias<<<grid, 256>>>(att, Wproj, bproj, out, ROWS, DMODEL, DMODEL);
    }
}

// round 9
// speedup vs baseline: 1.7235x; 1.7235x over previous
#include <cuda_runtime.h>
#include <cuda_bf16.h>
#include <cstdint>
#include <math.h>
#include <math_constants.h>

typedef unsigned int u32;

// Problem constants
#define BATCH 2
#define SEQ   2048
#define DMODEL 2048
#define NHEAD 16
#define HDIM  128
#define ROWS  (BATCH * SEQ)          // 4096
#define QKV_N (3 * DMODEL)           // 6144

// Scratch (allocation-free rule: __device__ globals)
__device__ float g_qkv[(size_t)ROWS * QKV_N];   // [4096, 6144]
__device__ float g_att[(size_t)ROWS * DMODEL];  // [4096, 2048]

// ---------------------------------------------------------------------------
// Helpers
// ---------------------------------------------------------------------------
__device__ __forceinline__ u32 f2tf32(float x) {
    u32 r;
    asm("cvt.rna.tf32.f32 %0, %1;" : "=r"(r) : "f"(x));
    return r;
}

__device__ __forceinline__ void cp_async16(u32 smem_addr, const void* gptr) {
    asm volatile("cp.async.cg.shared.global [%0], [%1], 16;\n"
                 :: "r"(smem_addr), "l"(gptr));
}
__device__ __forceinline__ void cp_commit() {
    asm volatile("cp.async.commit_group;\n" ::: "memory");
}
template <int N>
__device__ __forceinline__ void cp_wait() {
    asm volatile("cp.async.wait_group %0;\n" :: "n"(N) : "memory");
}

__device__ __forceinline__ void mma_tf32(float* c, const u32* a, const u32* b) {
    asm volatile(
        "mma.sync.aligned.m16n8k8.row.col.f32.tf32.tf32.f32 "
        "{%0,%1,%2,%3}, {%4,%5,%6,%7}, {%8,%9}, {%0,%1,%2,%3};\n"
        : "+f"(c[0]), "+f"(c[1]), "+f"(c[2]), "+f"(c[3])
        : "r"(a[0]), "r"(a[1]), "r"(a[2]), "r"(a[3]), "r"(b[0]), "r"(b[1]));
}

// ---------------------------------------------------------------------------
// TF32 tensor-core GEMM: C[M,N] = A[M,K] @ B[K,N] + bias[N]  (row-major fp32)
// 128x128 tile, BK=16, 2-stage cp.async pipeline, 8 warps, warp tile 32x64.
// ---------------------------------------------------------------------------
#define GBM 128
#define GBN 128
#define GBK 16
#define ASTR 20    // 16 + 4 pad (keeps 16B chunk alignment, conflict-free frags)
#define BSTR 136   // 128 + 8 pad

__global__ __launch_bounds__(256)
void gemm_tf32(const float* __restrict__ A, const float* __restrict__ B,
               const float* __restrict__ bias, float* __restrict__ C,
               int M, int N, int K) {
    __shared__ float As[2][GBM * ASTR];   // As[buf][m*20 + k]
    __shared__ float Bs[2][GBK * BSTR];   // Bs[buf][k*136 + n]

    const int tid = threadIdx.x;
    const int lane = tid & 31;
    const int wid  = tid >> 5;
    const int g = lane >> 2;       // 0..7
    const int t = lane & 3;        // 0..3
    const int warp_m = (wid & 3) * 32;   // 0,32,64,96
    const int warp_n = (wid >> 2) * 64;  // 0,64

    const int rowBase = blockIdx.y * GBM;
    const int colBase = blockIdx.x * GBN;

    // cp.async chunk mappings (each thread: 2 chunks of 16B for A, 2 for B)
    // A tile: 128 rows x 16 floats = 512 chunks. chunk c: row=c>>2, kc=(c&3)*4
    // B tile: 16 rows x 128 floats = 512 chunks. chunk c: row=c>>5, nc=(c&31)*4
    u32 asbase = (u32)__cvta_generic_to_shared(&As[0][0]);
    u32 bsbase = (u32)__cvta_generic_to_shared(&Bs[0][0]);

    float acc[2][8][4];
    #pragma unroll
    for (int i = 0; i < 2; i++)
        #pragma unroll
        for (int j = 0; j < 8; j++)
            #pragma unroll
            for (int v = 0; v < 4; v++) acc[i][j][v] = 0.0f;

    const int NT = K / GBK;

    // Prologue: load tile 0 into buf 0
    {
        #pragma unroll
        for (int it = 0; it < 2; it++) {
            int c = tid + it * 256;
            int ar = c >> 2, akc = (c & 3) * 4;
            cp_async16(asbase + (u32)(ar * ASTR + akc) * 4u,
                       &A[(size_t)(rowBase + ar) * K + akc]);
            int br = c >> 5, bnc = (c & 31) * 4;
            cp_async16(bsbase + (u32)(br * BSTR + bnc) * 4u,
                       &B[(size_t)br * N + colBase + bnc]);
        }
        cp_commit();
    }

    for (int kt = 0; kt < NT; kt++) {
        const int buf = kt & 1;
        // Issue next tile into buf^1
        if (kt + 1 < NT) {
            const int k0g = (kt + 1) * GBK;
            u32 asd = asbase + (u32)(buf ^ 1) * (GBM * ASTR * 4u);
            u32 bsd = bsbase + (u32)(buf ^ 1) * (GBK * BSTR * 4u);
            #pragma unroll
            for (int it = 0; it < 2; it++) {
                int c = tid + it * 256;
                int ar = c >> 2, akc = (c & 3) * 4;
                cp_async16(asd + (u32)(ar * ASTR + akc) * 4u,
                           &A[(size_t)(rowBase + ar) * K + k0g + akc]);
                int br = c >> 5, bnc = (c & 31) * 4;
                cp_async16(bsd + (u32)(br * BSTR + bnc) * 4u,
                           &B[(size_t)(k0g + br) * N + colBase + bnc]);
            }
        }
        cp_commit();
        cp_wait<1>();
        __syncthreads();

        const float* Ab = As[buf];
        const float* Bb = Bs[buf];
        #pragma unroll
        for (int ks = 0; ks < 2; ks++) {
            const int k0 = ks * 8;
            u32 af[2][4];
            u32 bf[8][2];
            #pragma unroll
            for (int mt = 0; mt < 2; mt++) {
                int m = warp_m + mt * 16 + g;
                af[mt][0] = f2tf32(Ab[m * ASTR + k0 + t]);
                af[mt][1] = f2tf32(Ab[(m + 8) * ASTR + k0 + t]);
                af[mt][2] = f2tf32(Ab[m * ASTR + k0 + t + 4]);
                af[mt][3] = f2tf32(Ab[(m + 8) * ASTR + k0 + t + 4]);
            }
            #pragma unroll
            for (int nt = 0; nt < 8; nt++) {
                int n = warp_n + nt * 8 + g;
                bf[nt][0] = f2tf32(Bb[(k0 + t) * BSTR + n]);
                bf[nt][1] = f2tf32(Bb[(k0 + t + 4) * BSTR + n]);
            }
            #pragma unroll
            for (int mt = 0; mt < 2; mt++)
                #pragma unroll
                for (int nt = 0; nt < 8; nt++)
                    mma_tf32(acc[mt][nt], af[mt], bf[nt]);
        }
        __syncthreads();
    }

    // Epilogue: bias + store (float2 per c-pair)
    #pragma unroll
    for (int mt = 0; mt < 2; mt++) {
        int row = rowBase + warp_m + mt * 16 + g;
        #pragma unroll
        for (int nt = 0; nt < 8; nt++) {
            int col = colBase + warp_n + nt * 8 + 2 * t;
            float b0 = bias[col], b1 = bias[col + 1];
            float2 v0 = make_float2(acc[mt][nt][0] + b0, acc[mt][nt][1] + b1);
            float2 v1 = make_float2(acc[mt][nt][2] + b0, acc[mt][nt][3] + b1);
            *(float2*)&C[(size_t)row * N + col] = v0;
            *(float2*)&C[(size_t)(row + 8) * N + col] = v1;
        }
    }
}

// ---------------------------------------------------------------------------
// Flash-attention, fp32 matmuls + register-resident online softmax (__expf).
// Grid: (S/64 q-tiles, H, B). Block: 256 threads.
// ---------------------------------------------------------------------------
#define QT 64
#define QPAD 132
#define SPAD 68
#define ATTN_SMEM_FLOATS (3 * QT * QPAD + QT * SPAD)
#define ATTN_SMEM_BYTES  (ATTN_SMEM_FLOATS * 4)

__global__ __launch_bounds__(256, 1)
void attn_kernel(const float* __restrict__ qkv, float* __restrict__ out) {
    extern __shared__ float sm[];
    float* Qs = sm;                         // 64*132
    float* Ks = Qs + QT * QPAD;             // 64*132
    float* Vs = Ks + QT * QPAD;             // 64*132
    float* Ss = Vs + QT * QPAD;             // 64*68

    const int qt  = gridDim.x - 1 - blockIdx.x;  // longest blocks first
    const int h   = blockIdx.y;
    const int b   = blockIdx.z;
    const int tid = threadIdx.x;
    const int ty  = tid / 16;               // 0..15
    const int tx  = tid % 16;               // 0..15
    const int r0  = ty * 4;
    const int c0  = tx * 4;
    const int oc0 = tx * 8;

    const float scale = 0.08838834764831845f;   // 1/sqrt(128)
    const size_t base = (size_t)b * SEQ * QKV_N;
    const int hoff = h * HDIM;

    for (int idx = tid; idx < QT * 32; idx += 256) {
        int r  = idx / 32;
        int d4 = (idx % 32) * 4;
        float4 v = *(const float4*)&qkv[base + (size_t)(qt * QT + r) * QKV_N + hoff + d4];
        *(float4*)&Qs[r * QPAD + d4] = v;
    }

    float m_run[4], l_run[4], O[4][8];
    #pragma unroll
    for (int i = 0; i < 4; i++) {
        m_run[i] = -CUDART_INF_F;
        l_run[i] = 0.0f;
        #pragma unroll
        for (int j = 0; j < 8; j++) O[i][j] = 0.0f;
    }

    for (int kt = 0; kt <= qt; kt++) {
        __syncthreads();   // prev iter done with Ks/Vs/Ss (and Qs visible iter 0)
        for (int idx = tid; idx < QT * 32; idx += 256) {
            int r  = idx / 32;
            int d4 = (idx % 32) * 4;
            size_t rowoff = base + (size_t)(kt * QT + r) * QKV_N + hoff;
            *(float4*)&Ks[r * QPAD + d4] = *(const float4*)&qkv[rowoff + DMODEL + d4];
            *(float4*)&Vs[r * QPAD + d4] = *(const float4*)&qkv[rowoff + 2 * DMODEL + d4];
        }
        __syncthreads();

        // S = scale * Q K^T  (4x4 per thread)
        float acc[4][4];
        #pragma unroll
        for (int i = 0; i < 4; i++)
            #pragma unroll
            for (int j = 0; j < 4; j++) acc[i][j] = 0.0f;

        for (int d = 0; d < HDIM; d += 4) {
            float4 qv[4], kv[4];
            #pragma unroll
            for (int i = 0; i < 4; i++) qv[i] = *(float4*)&Qs[(r0 + i) * QPAD + d];
            #pragma unroll
            for (int j = 0; j < 4; j++) kv[j] = *(float4*)&Ks[(c0 + j) * QPAD + d];
            #pragma unroll
            for (int i = 0; i < 4; i++)
                #pragma unroll
                for (int j = 0; j < 4; j++) {
                    acc[i][j] = fmaf(qv[i].x, kv[j].x, acc[i][j]);
                    acc[i][j] = fmaf(qv[i].y, kv[j].y, acc[i][j]);
                    acc[i][j] = fmaf(qv[i].z, kv[j].z, acc[i][j]);
                    acc[i][j] = fmaf(qv[i].w, kv[j].w, acc[i][j]);
                }
        }

        // scale + causal mask, in registers
        const bool diag = (kt == qt);
        #pragma unroll
        for (int i = 0; i < 4; i++)
            #pragma unroll
            for (int j = 0; j < 4; j++) {
                float s = acc[i][j] * scale;
                if (diag && (c0 + j) > (r0 + i)) s = -CUDART_INF_F;
                acc[i][j] = s;
            }

        // row-wise max across the 16 threads sharing each row (half-warp shfl)
        float fscale[4];
        #pragma unroll
        for (int i = 0; i < 4; i++) {
            float mt = fmaxf(fmaxf(acc[i][0], acc[i][1]), fmaxf(acc[i][2], acc[i][3]));
            #pragma unroll
            for (int off = 1; off < 16; off <<= 1)
                mt = fmaxf(mt, __shfl_xor_sync(0xffffffffu, mt, off));
            float mn = fmaxf(m_run[i], mt);
            fscale[i] = __expf(m_run[i] - mn);   // exp(-inf - finite) = 0 on iter 0
            m_run[i] = mn;
        }

        // p = exp(s - m), write to Ss, row-sum via shfl, update l, rescale O
        #pragma unroll
        for (int i = 0; i < 4; i++) {
            float sum = 0.0f;
            #pragma unroll
            for (int j = 0; j < 4; j++) {
                float p = __expf(acc[i][j] - m_run[i]);   // masked -> exp(-inf) = 0
                Ss[(r0 + i) * SPAD + (c0 + j)] = p;
                sum += p;
            }
            #pragma unroll
            for (int off = 1; off < 16; off <<= 1)
                sum += __shfl_xor_sync(0xffffffffu, sum, off);
            l_run[i] = l_run[i] * fscale[i] + sum;
            #pragma unroll
            for (int j = 0; j < 8; j++) O[i][j] *= fscale[i];
        }
        __syncthreads();

        // O += P @ V
        for (int k = 0; k < QT; k++) {
            float p[4];
            #pragma unroll
            for (int i = 0; i < 4; i++) p[i] = Ss[(r0 + i) * SPAD + k];
            float4 v0 = *(float4*)&Vs[k * QPAD + oc0];
            float4 v1 = *(float4*)&Vs[k * QPAD + oc0 + 4];
            #pragma unroll
            for (int i = 0; i < 4; i++) {
                O[i][0] = fmaf(p[i], v0.x, O[i][0]);
                O[i][1] = fmaf(p[i], v0.y, O[i][1]);
                O[i][2] = fmaf(p[i], v0.z, O[i][2]);
                O[i][3] = fmaf(p[i], v0.w, O[i][3]);
                O[i][4] = fmaf(p[i], v1.x, O[i][4]);
                O[i][5] = fmaf(p[i], v1.y, O[i][5]);
                O[i][6] = fmaf(p[i], v1.z, O[i][6]);
                O[i][7] = fmaf(p[i], v1.w, O[i][7]);
            }
        }
    }

    // Epilogue: O /= l
    float inv[4];
    #pragma unroll
    for (int i = 0; i < 4; i++) inv[i] = 1.0f / l_run[i];
    size_t obase = ((size_t)b * SEQ + (size_t)qt * QT) * DMODEL + hoff;
    #pragma unroll
    for (int i = 0; i < 4; i++) {
        #pragma unroll
        for (int j = 0; j < 8; j += 4) {
            float4 v;
            v.x = O[i][j + 0] * inv[i];
            v.y = O[i][j + 1] * inv[i];
            v.z = O[i][j + 2] * inv[i];
            v.w = O[i][j + 3] * inv[i];
            *(float4*)&out[obase + (size_t)(r0 + i) * DMODEL + oc0 + j] = v;
        }
    }
}

// ---------------------------------------------------------------------------
// Launch
// ---------------------------------------------------------------------------
extern "C" void kernel_launch(void* const* d_in, const int* in_sizes, int n_in,
                              void* d_out, int out_size) {
    const float* x     = (const float*)d_in[0];
    const float* Wqkv  = (const float*)d_in[1];
    const float* bqkv  = (const float*)d_in[2];
    const float* Wproj = (const float*)d_in[3];
    const float* bproj = (const float*)d_in[4];
    float* out = (float*)d_out;

    float* qkv;
    float* att;
    cudaGetSymbolAddress((void**)&qkv, g_qkv);
    cudaGetSymbolAddress((void**)&att, g_att);

    cudaFuncSetAttribute(attn_kernel, cudaFuncAttributeMaxDynamicSharedMemorySize,
                         ATTN_SMEM_BYTES);

    // 1) QKV GEMM: [4096,2048] @ [2048,6144] + bqkv
    {
        dim3 grid(QKV_N / GBN, ROWS / GBM);
        gemm_tf32<<<grid, 256>>>(x, Wqkv, bqkv, qkv, ROWS, QKV_N, DMODEL);
    }
    // 2) Causal attention
    {
        dim3 grid(SEQ / QT, NHEAD, BATCH);
        attn_kernel<<<grid, 256, ATTN_SMEM_BYTES>>>(qkv, att);
    }
    // 3) Proj GEMM: [4096,2048] @ [2048,2048] + bproj
    {
        dim3 grid(DMODEL / GBN, ROWS / GBM);
        gemm_tf32<<<grid, 256>>>(att, Wproj, bproj, out, ROWS, DMODEL, DMODEL);
    }
}

// round 10
// speedup vs baseline: 3.3495x; 1.9434x over previous
#include <cuda_runtime.h>
#include <cuda_bf16.h>
#include <cstdint>
#include <math.h>
#include <math_constants.h>

typedef unsigned int u32;

// Problem constants
#define BATCH 2
#define SEQ   2048
#define DMODEL 2048
#define NHEAD 16
#define HDIM  128
#define ROWS  (BATCH * SEQ)          // 4096
#define QKV_N (3 * DMODEL)           // 6144

// Scratch (allocation-free rule: __device__ globals)
__device__ float g_qkv[(size_t)ROWS * QKV_N];   // [4096, 6144]
__device__ float g_att[(size_t)ROWS * DMODEL];  // [4096, 2048]

// ---------------------------------------------------------------------------
// Helpers
// ---------------------------------------------------------------------------
__device__ __forceinline__ u32 f2tf32(float x) {
    u32 r;
    asm("cvt.rna.tf32.f32 %0, %1;" : "=r"(r) : "f"(x));
    return r;
}
__device__ __forceinline__ float tf32f(float x) {
    return __uint_as_float(f2tf32(x));
}

__device__ __forceinline__ void cp_async16(u32 smem_addr, const void* gptr) {
    asm volatile("cp.async.cg.shared.global [%0], [%1], 16;\n"
                 :: "r"(smem_addr), "l"(gptr));
}
__device__ __forceinline__ void cp_commit() {
    asm volatile("cp.async.commit_group;\n" ::: "memory");
}
template <int N>
__device__ __forceinline__ void cp_wait() {
    asm volatile("cp.async.wait_group %0;\n" :: "n"(N) : "memory");
}

__device__ __forceinline__ void mma_tf32(float* c, const u32* a, const u32* b) {
    asm volatile(
        "mma.sync.aligned.m16n8k8.row.col.f32.tf32.tf32.f32 "
        "{%0,%1,%2,%3}, {%4,%5,%6,%7}, {%8,%9}, {%0,%1,%2,%3};\n"
        : "+f"(c[0]), "+f"(c[1]), "+f"(c[2]), "+f"(c[3])
        : "r"(a[0]), "r"(a[1]), "r"(a[2]), "r"(a[3]), "r"(b[0]), "r"(b[1]));
}

// ---------------------------------------------------------------------------
// TF32 tensor-core GEMM: C[M,N] = A[M,K] @ B[K,N] + bias[N]  (row-major fp32)
// (unchanged from Round 9)
// ---------------------------------------------------------------------------
#define GBM 128
#define GBN 128
#define GBK 16
#define ASTR 20
#define BSTR 136

__global__ __launch_bounds__(256)
void gemm_tf32(const float* __restrict__ A, const float* __restrict__ B,
               const float* __restrict__ bias, float* __restrict__ C,
               int M, int N, int K) {
    __shared__ float As[2][GBM * ASTR];
    __shared__ float Bs[2][GBK * BSTR];

    const int tid = threadIdx.x;
    const int lane = tid & 31;
    const int wid  = tid >> 5;
    const int g = lane >> 2;
    const int t = lane & 3;
    const int warp_m = (wid & 3) * 32;
    const int warp_n = (wid >> 2) * 64;

    const int rowBase = blockIdx.y * GBM;
    const int colBase = blockIdx.x * GBN;

    u32 asbase = (u32)__cvta_generic_to_shared(&As[0][0]);
    u32 bsbase = (u32)__cvta_generic_to_shared(&Bs[0][0]);

    float acc[2][8][4];
    #pragma unroll
    for (int i = 0; i < 2; i++)
        #pragma unroll
        for (int j = 0; j < 8; j++)
            #pragma unroll
            for (int v = 0; v < 4; v++) acc[i][j][v] = 0.0f;

    const int NT = K / GBK;

    {
        #pragma unroll
        for (int it = 0; it < 2; it++) {
            int c = tid + it * 256;
            int ar = c >> 2, akc = (c & 3) * 4;
            cp_async16(asbase + (u32)(ar * ASTR + akc) * 4u,
                       &A[(size_t)(rowBase + ar) * K + akc]);
            int br = c >> 5, bnc = (c & 31) * 4;
            cp_async16(bsbase + (u32)(br * BSTR + bnc) * 4u,
                       &B[(size_t)br * N + colBase + bnc]);
        }
        cp_commit();
    }

    for (int kt = 0; kt < NT; kt++) {
        const int buf = kt & 1;
        if (kt + 1 < NT) {
            const int k0g = (kt + 1) * GBK;
            u32 asd = asbase + (u32)(buf ^ 1) * (GBM * ASTR * 4u);
            u32 bsd = bsbase + (u32)(buf ^ 1) * (GBK * BSTR * 4u);
            #pragma unroll
            for (int it = 0; it < 2; it++) {
                int c = tid + it * 256;
                int ar = c >> 2, akc = (c & 3) * 4;
                cp_async16(asd + (u32)(ar * ASTR + akc) * 4u,
                           &A[(size_t)(rowBase + ar) * K + k0g + akc]);
                int br = c >> 5, bnc = (c & 31) * 4;
                cp_async16(bsd + (u32)(br * BSTR + bnc) * 4u,
                           &B[(size_t)(k0g + br) * N + colBase + bnc]);
            }
        }
        cp_commit();
        cp_wait<1>();
        __syncthreads();

        const float* Ab = As[buf];
        const float* Bb = Bs[buf];
        #pragma unroll
        for (int ks = 0; ks < 2; ks++) {
            const int k0 = ks * 8;
            u32 af[2][4];
            u32 bf[8][2];
            #pragma unroll
            for (int mt = 0; mt < 2; mt++) {
                int m = warp_m + mt * 16 + g;
                af[mt][0] = f2tf32(Ab[m * ASTR + k0 + t]);
                af[mt][1] = f2tf32(Ab[(m + 8) * ASTR + k0 + t]);
                af[mt][2] = f2tf32(Ab[m * ASTR + k0 + t + 4]);
                af[mt][3] = f2tf32(Ab[(m + 8) * ASTR + k0 + t + 4]);
            }
            #pragma unroll
            for (int nt = 0; nt < 8; nt++) {
                int n = warp_n + nt * 8 + g;
                bf[nt][0] = f2tf32(Bb[(k0 + t) * BSTR + n]);
                bf[nt][1] = f2tf32(Bb[(k0 + t + 4) * BSTR + n]);
            }
            #pragma unroll
            for (int mt = 0; mt < 2; mt++)
                #pragma unroll
                for (int nt = 0; nt < 8; nt++)
                    mma_tf32(acc[mt][nt], af[mt], bf[nt]);
        }
        __syncthreads();
    }

    #pragma unroll
    for (int mt = 0; mt < 2; mt++) {
        int row = rowBase + warp_m + mt * 16 + g;
        #pragma unroll
        for (int nt = 0; nt < 8; nt++) {
            int col = colBase + warp_n + nt * 8 + 2 * t;
            float b0 = bias[col], b1 = bias[col + 1];
            float2 v0 = make_float2(acc[mt][nt][0] + b0, acc[mt][nt][1] + b1);
            float2 v1 = make_float2(acc[mt][nt][2] + b0, acc[mt][nt][3] + b1);
            *(float2*)&C[(size_t)row * N + col] = v0;
            *(float2*)&C[(size_t)(row + 8) * N + col] = v1;
        }
    }
}

// ---------------------------------------------------------------------------
// Flash attention with tf32 tensor-core mma for QK^T and P@V.
// Grid: (S/64, H, B), 256 threads (8 warps).
// Warp layout: wm = (w&3)*16 (q-rows), wh = w>>2 (N-half).
//   S: warp computes rows [wm,wm+16) x key-cols [wh*32, wh*32+32)
//   O: warp computes rows [wm,wm+16) x d-cols  [wh*64, wh*64+64)
// Q/K/V/P stored in smem pre-rounded to tf32 (cvt idempotent -> raw bit loads).
// Q pre-scaled by 1/sqrt(dh). Online softmax state in registers, cross-warp
// row max/sum exchanged via pmax/psum smem.
// ---------------------------------------------------------------------------
#define QT 64
#define QPAD 132        // stride 132 = 4 mod 32 -> conflict-free frag loads
#define SPAD 68
#define AQ_FLOATS (QT * QPAD)              // 8448
#define AS_FLOATS (QT * SPAD)              // 4352
#define ATTN_SMEM_FLOATS (3 * AQ_FLOATS + AS_FLOATS + 2 * 128)
#define ATTN_SMEM_BYTES  (ATTN_SMEM_FLOATS * 4)

__global__ __launch_bounds__(256, 1)
void attn_mma(const float* __restrict__ qkv, float* __restrict__ out) {
    extern __shared__ float sm[];
    float* Qs   = sm;                     // [64][132] tf32, pre-scaled
    float* Ks   = Qs + AQ_FLOATS;         // [64][132] tf32
    float* Vs   = Ks + AQ_FLOATS;         // [64][132] tf32
    float* Ss   = Vs + AQ_FLOATS;         // [64][68]  P, tf32
    float* pmax = Ss + AS_FLOATS;         // [64][2]
    float* psum = pmax + 128;             // [64][2]

    const int qt  = gridDim.x - 1 - blockIdx.x;  // longest blocks first
    const int h   = blockIdx.y;
    const int b   = blockIdx.z;
    const int tid = threadIdx.x;
    const int lane = tid & 31;
    const int w    = tid >> 5;
    const int g    = lane >> 2;          // 0..7
    const int t    = lane & 3;           // 0..3
    const int wm   = (w & 3) * 16;       // q-row stripe
    const int wh   = w >> 2;             // 0/1
    const int wn   = wh * 32;            // key-col base (S)
    const int wd   = wh * 64;            // d-col base (O)

    const float scale = 0.08838834764831845f;   // 1/sqrt(128)
    const size_t base = (size_t)b * SEQ * QKV_N;
    const int hoff = h * HDIM;

    // Load Q tile: tf32-round and fold in softmax scale
    for (int idx = tid; idx < QT * 32; idx += 256) {
        int r  = idx >> 5;
        int d4 = (idx & 31) * 4;
        float4 v = *(const float4*)&qkv[base + (size_t)(qt * QT + r) * QKV_N + hoff + d4];
        Qs[r * QPAD + d4 + 0] = tf32f(v.x * scale);
        Qs[r * QPAD + d4 + 1] = tf32f(v.y * scale);
        Qs[r * QPAD + d4 + 2] = tf32f(v.z * scale);
        Qs[r * QPAD + d4 + 3] = tf32f(v.w * scale);
    }

    // Per-thread state: rows wm+g and wm+8+g
    float m_run[2] = { -CUDART_INF_F, -CUDART_INF_F };
    float l_run[2] = { 0.0f, 0.0f };
    float O[8][4];
    #pragma unroll
    for (int dbl = 0; dbl < 8; dbl++)
        #pragma unroll
        for (int v = 0; v < 4; v++) O[dbl][v] = 0.0f;

    for (int kt = 0; kt <= qt; kt++) {
        __syncthreads();   // prev iter done reading Ks/Vs/Ss (Qs visible iter 0)
        for (int idx = tid; idx < QT * 32; idx += 256) {
            int r  = idx >> 5;
            int d4 = (idx & 31) * 4;
            size_t rowoff = base + (size_t)(kt * QT + r) * QKV_N + hoff;
            float4 kv = *(const float4*)&qkv[rowoff + DMODEL + d4];
            float4 vv = *(const float4*)&qkv[rowoff + 2 * DMODEL + d4];
            Ks[r * QPAD + d4 + 0] = tf32f(kv.x);
            Ks[r * QPAD + d4 + 1] = tf32f(kv.y);
            Ks[r * QPAD + d4 + 2] = tf32f(kv.z);
            Ks[r * QPAD + d4 + 3] = tf32f(kv.w);
            Vs[r * QPAD + d4 + 0] = tf32f(vv.x);
            Vs[r * QPAD + d4 + 1] = tf32f(vv.y);
            Vs[r * QPAD + d4 + 2] = tf32f(vv.z);
            Vs[r * QPAD + d4 + 3] = tf32f(vv.w);
        }
        __syncthreads();

        // ---- S = Qs @ Ks^T (scale already folded into Q) ----
        float sa[4][4];
        #pragma unroll
        for (int nb = 0; nb < 4; nb++)
            #pragma unroll
            for (int v = 0; v < 4; v++) sa[nb][v] = 0.0f;

        #pragma unroll
        for (int ks = 0; ks < 16; ks++) {
            const int k0 = ks * 8;
            u32 A[4];
            A[0] = __float_as_uint(Qs[(wm + g) * QPAD + k0 + t]);
            A[1] = __float_as_uint(Qs[(wm + 8 + g) * QPAD + k0 + t]);
            A[2] = __float_as_uint(Qs[(wm + g) * QPAD + k0 + t + 4]);
            A[3] = __float_as_uint(Qs[(wm + 8 + g) * QPAD + k0 + t + 4]);
            #pragma unroll
            for (int nb = 0; nb < 4; nb++) {
                const int n0 = wn + nb * 8;
                u32 Bq[2];
                Bq[0] = __float_as_uint(Ks[(n0 + g) * QPAD + k0 + t]);
                Bq[1] = __float_as_uint(Ks[(n0 + g) * QPAD + k0 + t + 4]);
                mma_tf32(sa[nb], A, Bq);
            }
        }

        // ---- causal mask (fragment: c0,c1 row g; c2,c3 row g+8; cols 2t,2t+1)
        if (kt == qt) {
            #pragma unroll
            for (int nb = 0; nb < 4; nb++) {
                const int c0 = wn + nb * 8 + 2 * t;
                if (c0     > wm + g)     sa[nb][0] = -CUDART_INF_F;
                if (c0 + 1 > wm + g)     sa[nb][1] = -CUDART_INF_F;
                if (c0     > wm + 8 + g) sa[nb][2] = -CUDART_INF_F;
                if (c0 + 1 > wm + 8 + g) sa[nb][3] = -CUDART_INF_F;
            }
        }

        // ---- row max within this warp's 32-col half ----
        float tmax[2];
        tmax[0] = fmaxf(fmaxf(sa[0][0], sa[0][1]), fmaxf(sa[1][0], sa[1][1]));
        tmax[0] = fmaxf(tmax[0], fmaxf(fmaxf(sa[2][0], sa[2][1]), fmaxf(sa[3][0], sa[3][1])));
        tmax[1] = fmaxf(fmaxf(sa[0][2], sa[0][3]), fmaxf(sa[1][2], sa[1][3]));
        tmax[1] = fmaxf(tmax[1], fmaxf(fmaxf(sa[2][2], sa[2][3]), fmaxf(sa[3][2], sa[3][3])));
        #pragma unroll
        for (int i = 0; i < 2; i++) {
            tmax[i] = fmaxf(tmax[i], __shfl_xor_sync(0xffffffffu, tmax[i], 1));
            tmax[i] = fmaxf(tmax[i], __shfl_xor_sync(0xffffffffu, tmax[i], 2));
        }
        if (t == 0) {
            pmax[(wm + g) * 2 + wh]     = tmax[0];
            pmax[(wm + 8 + g) * 2 + wh] = tmax[1];
        }
        __syncthreads();

        float fs[2];
        #pragma unroll
        for (int i = 0; i < 2; i++) {
            const int r = wm + g + 8 * i;
            float mt2 = fmaxf(pmax[r * 2 + 0], pmax[r * 2 + 1]);
            float mn = fmaxf(m_run[i], mt2);
            fs[i] = __expf(m_run[i] - mn);     // 0 on first iter
            m_run[i] = mn;
        }

        // ---- p = exp(s-m) (tf32-rounded), store to Ss, partial row sums ----
        float tsum[2] = { 0.0f, 0.0f };
        #pragma unroll
        for (int nb = 0; nb < 4; nb++) {
            float p0 = tf32f(__expf(sa[nb][0] - m_run[0]));
            float p1 = tf32f(__expf(sa[nb][1] - m_run[0]));
            float p2 = tf32f(__expf(sa[nb][2] - m_run[1]));
            float p3 = tf32f(__expf(sa[nb][3] - m_run[1]));
            tsum[0] += p0 + p1;
            tsum[1] += p2 + p3;
            const int col = wn + nb * 8 + 2 * t;
            *(float2*)&Ss[(wm + g) * SPAD + col]     = make_float2(p0, p1);
            *(float2*)&Ss[(wm + 8 + g) * SPAD + col] = make_float2(p2, p3);
        }
        #pragma unroll
        for (int i = 0; i < 2; i++) {
            tsum[i] += __shfl_xor_sync(0xffffffffu, tsum[i], 1);
            tsum[i] += __shfl_xor_sync(0xffffffffu, tsum[i], 2);
        }
        if (t == 0) {
            psum[(wm + g) * 2 + wh]     = tsum[0];
            psum[(wm + 8 + g) * 2 + wh] = tsum[1];
        }
        __syncthreads();

        #pragma unroll
        for (int i = 0; i < 2; i++) {
            const int r = wm + g + 8 * i;
            l_run[i] = l_run[i] * fs[i] + psum[r * 2 + 0] + psum[r * 2 + 1];
        }

        // ---- rescale O, then O += P @ V ----
        #pragma unroll
        for (int dbl = 0; dbl < 8; dbl++) {
            O[dbl][0] *= fs[0];
            O[dbl][1] *= fs[0];
            O[dbl][2] *= fs[1];
            O[dbl][3] *= fs[1];
        }
        #pragma unroll
        for (int ks = 0; ks < 8; ks++) {
            const int k0 = ks * 8;
            u32 A[4];
            A[0] = __float_as_uint(Ss[(wm + g) * SPAD + k0 + t]);
            A[1] = __float_as_uint(Ss[(wm + 8 + g) * SPAD + k0 + t]);
            A[2] = __float_as_uint(Ss[(wm + g) * SPAD + k0 + t + 4]);
            A[3] = __float_as_uint(Ss[(wm + 8 + g) * SPAD + k0 + t + 4]);
            #pragma unroll
            for (int dbl = 0; dbl < 8; dbl++) {
                const int d0 = wd + dbl * 8;
                u32 Bv[2];
                Bv[0] = __float_as_uint(Vs[(k0 + t) * QPAD + d0 + g]);
                Bv[1] = __float_as_uint(Vs[(k0 + t + 4) * QPAD + d0 + g]);
                mma_tf32(O[dbl], A, Bv);
            }
        }
    }

    // Epilogue: O /= l, write out[b][q][hoff + d]
    float inv0 = 1.0f / l_run[0];
    float inv1 = 1.0f / l_run[1];
    const size_t obase = ((size_t)b * SEQ + (size_t)qt * QT) * DMODEL + hoff;
    #pragma unroll
    for (int dbl = 0; dbl < 8; dbl++) {
        const int col = wd + dbl * 8 + 2 * t;
        float2 v0 = make_float2(O[dbl][0] * inv0, O[dbl][1] * inv0);
        float2 v1 = make_float2(O[dbl][2] * inv1, O[dbl][3] * inv1);
        *(float2*)&out[obase + (size_t)(wm + g) * DMODEL + col] = v0;
        *(float2*)&out[obase + (size_t)(wm + 8 + g) * DMODEL + col] = v1;
    }
}

// ---------------------------------------------------------------------------
// Launch
// ---------------------------------------------------------------------------
extern "C" void kernel_launch(void* const* d_in, const int* in_sizes, int n_in,
                              void* d_out, int out_size) {
    const float* x     = (const float*)d_in[0];
    const float* Wqkv  = (const float*)d_in[1];
    const float* bqkv  = (const float*)d_in[2];
    const float* Wproj = (const float*)d_in[3];
    const float* bproj = (const float*)d_in[4];
    float* out = (float*)d_out;

    float* qkv;
    float* att;
    cudaGetSymbolAddress((void**)&qkv, g_qkv);
    cudaGetSymbolAddress((void**)&att, g_att);

    cudaFuncSetAttribute(attn_mma, cudaFuncAttributeMaxDynamicSharedMemorySize,
                         ATTN_SMEM_BYTES);

    // 1) QKV GEMM: [4096,2048] @ [2048,6144] + bqkv
    {
        dim3 grid(QKV_N / GBN, ROWS / GBM);
        gemm_tf32<<<grid, 256>>>(x, Wqkv, bqkv, qkv, ROWS, QKV_N, DMODEL);
    }
    // 2) Causal attention (tf32 mma)
    {
        dim3 grid(SEQ / QT, NHEAD, BATCH);
        attn_mma<<<grid, 256, ATTN_SMEM_BYTES>>>(qkv, att);
    }
    // 3) Proj GEMM: [4096,2048] @ [2048,2048] + bproj
    {
        dim3 grid(DMODEL / GBN, ROWS / GBM);
        gemm_tf32<<<grid, 256>>>(att, Wproj, bproj, out, ROWS, DMODEL, DMODEL);
    }
}